// round 15
// baseline (speedup 1.0000x reference)
#include <cuda_runtime.h>
#include <cuda_fp16.h>
#include <cfloat>
#include <cstdint>

// ===========================================================================
// SimpleAttention 4096x4096, sm_103 legacy tensor path (tcgen05 unavailable on
// the plain sm_103 PTX target; s8 IMMA ~4x slow; fp16-acc rate-neutral).
//   sims = feats @ feats^T / 4096   GEMM1: 128x128 CTA tiles, 8 warps,
//                                   symmetric (upper + mirror), fp16 out.
//   attn = softmax(sims, diag masked) -> fp16
//   out  = attn @ feats^T / 64      GEMM2: 128x64 CTA tiles, 4 warps,
//                                   3 CTAs/SM (12 warps/SM breaks the
//                                   power-of-2 wave quantization: 2048 CTAs /
//                                   444 slots = 4.61 -> 92.3% tail util vs
//                                   86.5% at 16 warps/SM).
// ===========================================================================

constexpr int NMAT = 4096;
constexpr int NSTEPS = 64;                // 4096 / 64
constexpr int TILEB = 128 * 128;          // bytes per 128-row operand tile
constexpr int STAGE1 = 2 * TILEB;         // GEMM1 stage: A128 + B128 = 32 KB
constexpr int NSTAGE = 3;
constexpr int SMEM1 = NSTAGE * STAGE1;    // 96 KB
constexpr int BTILE2 = 64 * 128;          // GEMM2 B tile: 64 rows
constexpr int STAGE2 = TILEB + BTILE2;    // 24 KB
constexpr int SMEM2 = NSTAGE * STAGE2;    // 72 KB
constexpr int TPAD = 132;                 // transpose buffer row stride

// ---- device scratch (allocation-free) -------------------------------------
__device__ __half g_sims[(size_t)NMAT * NMAT];
__device__ __half g_xh[(size_t)NMAT * NMAT];
__device__ __half g_ah[(size_t)NMAT * NMAT];

// ---- helpers --------------------------------------------------------------
#define SWZ(o) ((o) ^ (((o) >> 3) & 0x70))

__device__ __forceinline__ uint32_t smem_u32(const void* p) {
    uint32_t a;
    asm("{ .reg .u64 t; cvta.to.shared.u64 t, %1; cvt.u32.u64 %0, t; }"
        : "=r"(a) : "l"(p));
    return a;
}
__device__ __forceinline__ void cp_async16(uint32_t dst, const void* src) {
    asm volatile("cp.async.cg.shared.global [%0], [%1], 16;"
                 :: "r"(dst), "l"(src));
}
__device__ __forceinline__ void cp_commit() {
    asm volatile("cp.async.commit_group;" ::: "memory");
}
template <int N>
__device__ __forceinline__ void cp_wait() {
    asm volatile("cp.async.wait_group %0;" :: "n"(N) : "memory");
}
__device__ __forceinline__ void ldsm_x4(uint32_t addr, uint32_t r[4]) {
    asm volatile("ldmatrix.sync.aligned.m8n8.x4.shared.b16 {%0,%1,%2,%3}, [%4];"
                 : "=r"(r[0]), "=r"(r[1]), "=r"(r[2]), "=r"(r[3]) : "r"(addr));
}
__device__ __forceinline__ void mma_f16(float d[4], const uint32_t a[4],
                                        uint32_t b0, uint32_t b1) {
    asm volatile(
        "mma.sync.aligned.m16n8k16.row.col.f32.f16.f16.f32 "
        "{%0,%1,%2,%3}, {%4,%5,%6,%7}, {%8,%9}, {%0,%1,%2,%3};"
        : "+f"(d[0]), "+f"(d[1]), "+f"(d[2]), "+f"(d[3])
        : "r"(a[0]), "r"(a[1]), "r"(a[2]), "r"(a[3]), "r"(b0), "r"(b1));
}

// ===========================================================================
// GEMM1 (symmetric): sims tile 128x128, 8 warps (64x32 warp tiles), fp16 out.
// Only tiles by <= bx computed; off-diagonal tiles mirror-written transposed.
// ===========================================================================
__global__ __launch_bounds__(256, 2)
void gemm_sym(const __half* __restrict__ A, __half* __restrict__ C, float alpha)
{
    if (blockIdx.y > blockIdx.x) return;

    extern __shared__ char smem[];
    const uint32_t sbase = smem_u32(smem);

    const int tid  = threadIdx.x;
    const int warp = tid >> 5;
    const int lane = tid & 31;
    const int wm   = (warp & 1) * 64;
    const int wn   = (warp >> 1) * 32;
    const int rowBase = blockIdx.y * 128;
    const int colBase = blockIdx.x * 128;

    const size_t rowB = (size_t)NMAT * 2;
    const char* gA = (const char*)(A + (size_t)rowBase * NMAT);
    const char* gB = (const char*)(A + (size_t)colBase * NMAT);

    const int mA  = (lane & 7) + ((lane >> 3) & 1) * 8;
    const int kAo = ((lane >> 4) & 1) * 16;
    const int nB  = (lane & 7) + ((lane >> 4) & 1) * 8;
    const int kBo = ((lane >> 3) & 1) * 16;

    float acc[4][4][4];
#pragma unroll
    for (int i = 0; i < 4; i++)
#pragma unroll
        for (int j = 0; j < 4; j++)
#pragma unroll
            for (int t = 0; t < 4; t++) acc[i][j][t] = 0.0f;

    auto load_stage = [&](int kt) {
        if (kt < NSTEPS) {
            const uint32_t st = sbase + (kt % NSTAGE) * STAGE1;
            const size_t kOff = (size_t)kt * 128;
#pragma unroll
            for (int l = 0; l < 4; l++) {
                const int i = tid + l * 256;
                const int r = i >> 3, c = (i & 7) << 4;
                cp_async16(st + SWZ(r * 128 + c),
                           gA + (size_t)r * rowB + kOff + c);
            }
#pragma unroll
            for (int l = 0; l < 4; l++) {
                const int i = tid + l * 256;
                const int r = i >> 3, c = (i & 7) << 4;
                cp_async16(st + TILEB + SWZ(r * 128 + c),
                           gB + (size_t)r * rowB + kOff + c);
            }
        }
        cp_commit();
    };

    load_stage(0);
    load_stage(1);

    for (int kt = 0; kt < NSTEPS; kt++) {
        cp_wait<NSTAGE - 2>();
        __syncthreads();
        load_stage(kt + NSTAGE - 1);

        const uint32_t st = sbase + (kt % NSTAGE) * STAGE1;
#pragma unroll
        for (int ck = 0; ck < 4; ck++) {
            const int kb = ck * 32;
            uint32_t a[4][4];
#pragma unroll
            for (int mi = 0; mi < 4; mi++)
                ldsm_x4(st + SWZ((wm + mi * 16 + mA) * 128 + kb + kAo), a[mi]);
            uint32_t b[2][4];
#pragma unroll
            for (int nb = 0; nb < 2; nb++)
                ldsm_x4(st + TILEB + SWZ((wn + nb * 16 + nB) * 128 + kb + kBo),
                        b[nb]);
#pragma unroll
            for (int mi = 0; mi < 4; mi++)
#pragma unroll
                for (int nb = 0; nb < 2; nb++)
#pragma unroll
                    for (int h = 0; h < 2; h++)
                        mma_f16(acc[mi][nb * 2 + h], a[mi],
                                b[nb][2 * h], b[nb][2 * h + 1]);
        }
    }

#pragma unroll
    for (int mi = 0; mi < 4; mi++)
#pragma unroll
        for (int nj = 0; nj < 4; nj++)
#pragma unroll
            for (int t = 0; t < 4; t++) acc[mi][nj][t] *= alpha;

    const int rq = lane >> 2, cq = (lane & 3) * 2;
#pragma unroll
    for (int mi = 0; mi < 4; mi++) {
        const int row0 = rowBase + wm + mi * 16 + rq;
#pragma unroll
        for (int nj = 0; nj < 4; nj++) {
            const int col = colBase + wn + nj * 8 + cq;
            *(__half2*)&C[(size_t)row0 * NMAT + col] =
                __floats2half2_rn(acc[mi][nj][0], acc[mi][nj][1]);
            *(__half2*)&C[(size_t)(row0 + 8) * NMAT + col] =
                __floats2half2_rn(acc[mi][nj][2], acc[mi][nj][3]);
        }
    }

    if (blockIdx.x != blockIdx.y) {
        __syncthreads();
        float* T = (float*)smem;  // [128][TPAD] floats = 67.6 KB <= 96 KB
#pragma unroll
        for (int mi = 0; mi < 4; mi++) {
            const int r0 = wm + mi * 16 + rq;
#pragma unroll
            for (int nj = 0; nj < 4; nj++) {
                const int c0 = wn + nj * 8 + cq;
                T[(c0 + 0) * TPAD + r0]     = acc[mi][nj][0];
                T[(c0 + 1) * TPAD + r0]     = acc[mi][nj][1];
                T[(c0 + 0) * TPAD + r0 + 8] = acc[mi][nj][2];
                T[(c0 + 1) * TPAD + r0 + 8] = acc[mi][nj][3];
            }
        }
        __syncthreads();
#pragma unroll 4
        for (int rb = 0; rb < 128; rb += 8) {
            const int rr = rb + warp;
            const float4 v = *(const float4*)&T[rr * TPAD + (lane << 2)];
            __half2 h0 = __floats2half2_rn(v.x, v.y);
            __half2 h1 = __floats2half2_rn(v.z, v.w);
            *(uint2*)&C[(size_t)(colBase + rr) * NMAT + rowBase + (lane << 2)] =
                make_uint2(*(uint32_t*)&h0, *(uint32_t*)&h1);
        }
    }
}

// ===========================================================================
// GEMM2 (full): out tile 128x64, 4 warps (64x32 warp tiles), 3 CTAs/SM.
// ===========================================================================
__global__ __launch_bounds__(128, 3)
void gemm_full(const __half* __restrict__ A, const __half* __restrict__ B,
               float* __restrict__ C, float alpha)
{
    extern __shared__ char smem[];
    const uint32_t sbase = smem_u32(smem);

    const int tid  = threadIdx.x;
    const int warp = tid >> 5;
    const int lane = tid & 31;
    const int wm   = (warp & 1) * 64;    // 0, 64
    const int wn   = (warp >> 1) * 32;   // 0, 32
    const int rowBase = blockIdx.y * 128;
    const int colBase = blockIdx.x * 64;

    const size_t rowB = (size_t)NMAT * 2;
    const char* gA = (const char*)(A + (size_t)rowBase * NMAT);
    const char* gB = (const char*)(B + (size_t)colBase * NMAT);

    const int mA  = (lane & 7) + ((lane >> 3) & 1) * 8;
    const int kAo = ((lane >> 4) & 1) * 16;
    const int nB  = (lane & 7) + ((lane >> 4) & 1) * 8;
    const int kBo = ((lane >> 3) & 1) * 16;

    float acc[4][4][4];
#pragma unroll
    for (int i = 0; i < 4; i++)
#pragma unroll
        for (int j = 0; j < 4; j++)
#pragma unroll
            for (int t = 0; t < 4; t++) acc[i][j][t] = 0.0f;

    auto load_stage = [&](int kt) {
        if (kt < NSTEPS) {
            const uint32_t st = sbase + (kt % NSTAGE) * STAGE2;
            const size_t kOff = (size_t)kt * 128;
#pragma unroll
            for (int l = 0; l < 8; l++) {        // A: 128 rows x 8 chunks
                const int i = tid + l * 128;
                const int r = i >> 3, c = (i & 7) << 4;
                cp_async16(st + SWZ(r * 128 + c),
                           gA + (size_t)r * rowB + kOff + c);
            }
#pragma unroll
            for (int l = 0; l < 4; l++) {        // B: 64 rows x 8 chunks
                const int i = tid + l * 128;
                const int r = i >> 3, c = (i & 7) << 4;
                cp_async16(st + TILEB + SWZ(r * 128 + c),
                           gB + (size_t)r * rowB + kOff + c);
            }
        }
        cp_commit();
    };

    load_stage(0);
    load_stage(1);

    for (int kt = 0; kt < NSTEPS; kt++) {
        cp_wait<NSTAGE - 2>();
        __syncthreads();
        load_stage(kt + NSTAGE - 1);

        const uint32_t st = sbase + (kt % NSTAGE) * STAGE2;
#pragma unroll
        for (int ck = 0; ck < 4; ck++) {
            const int kb = ck * 32;
            uint32_t a[4][4];
#pragma unroll
            for (int mi = 0; mi < 4; mi++)
                ldsm_x4(st + SWZ((wm + mi * 16 + mA) * 128 + kb + kAo), a[mi]);
            uint32_t b[2][4];
#pragma unroll
            for (int nb = 0; nb < 2; nb++)
                ldsm_x4(st + TILEB + SWZ((wn + nb * 16 + nB) * 128 + kb + kBo),
                        b[nb]);
#pragma unroll
            for (int mi = 0; mi < 4; mi++)
#pragma unroll
                for (int nb = 0; nb < 2; nb++)
#pragma unroll
                    for (int h = 0; h < 2; h++)
                        mma_f16(acc[mi][nb * 2 + h], a[mi],
                                b[nb][2 * h], b[nb][2 * h + 1]);
        }
    }

    const int rq = lane >> 2, cq = (lane & 3) * 2;
#pragma unroll
    for (int mi = 0; mi < 4; mi++) {
        const int row0 = rowBase + wm + mi * 16 + rq;
#pragma unroll
        for (int nj = 0; nj < 4; nj++) {
            const int col = colBase + wn + nj * 8 + cq;
            *(float2*)&C[(size_t)row0 * NMAT + col] =
                make_float2(acc[mi][nj][0] * alpha, acc[mi][nj][1] * alpha);
            *(float2*)&C[(size_t)(row0 + 8) * NMAT + col] =
                make_float2(acc[mi][nj][2] * alpha, acc[mi][nj][3] * alpha);
        }
    }
}

// ===========================================================================
// feats fp32 -> fp16
// ===========================================================================
__global__ __launch_bounds__(256)
void conv_f16(const float* __restrict__ x, __half* __restrict__ h)
{
    const size_t i = (size_t)blockIdx.x * blockDim.x + threadIdx.x;
    const float4 v = ((const float4*)x)[i];
    __half2* hp = (__half2*)h;
    hp[2 * i]     = __floats2half2_rn(v.x, v.y);
    hp[2 * i + 1] = __floats2half2_rn(v.z, v.w);
}

// ===========================================================================
// Row softmax over fp16 sims with diag mask; emits fp16 attn.
// ===========================================================================
__global__ __launch_bounds__(256)
void softmax_rows(const __half* __restrict__ S, __half* __restrict__ ah)
{
    const int row = blockIdx.x;
    const int tid = threadIdx.x;
    const __half2* p = (const __half2*)(S + (size_t)row * NMAT);

    float v[16];
    float m = -FLT_MAX;
#pragma unroll
    for (int i = 0; i < 8; i++) {
        const int j2 = tid + i * 256;
        const float2 f = __half22float2(p[j2]);
        v[2 * i] = f.x;
        v[2 * i + 1] = f.y;
        const int j = 2 * j2;
        if (j != row)     m = fmaxf(m, f.x);
        if (j + 1 != row) m = fmaxf(m, f.y);
    }

    __shared__ float red[256];
    red[tid] = m;
    __syncthreads();
#pragma unroll
    for (int s = 128; s > 0; s >>= 1) {
        if (tid < s) red[tid] = fmaxf(red[tid], red[tid + s]);
        __syncthreads();
    }
    m = red[0];
    __syncthreads();

    float sum = 0.0f;
#pragma unroll
    for (int i = 0; i < 8; i++) {
        const int j = 2 * (tid + i * 256);
        float e0 = (j == row)     ? 0.0f : __expf(v[2 * i] - m);
        float e1 = (j + 1 == row) ? 0.0f : __expf(v[2 * i + 1] - m);
        v[2 * i] = e0;
        v[2 * i + 1] = e1;
        sum += e0 + e1;
    }
    red[tid] = sum;
    __syncthreads();
#pragma unroll
    for (int s = 128; s > 0; s >>= 1) {
        if (tid < s) red[tid] += red[tid + s];
        __syncthreads();
    }
    const float inv = 1.0f / red[0];

    __half2* arow = (__half2*)(ah + (size_t)row * NMAT);
#pragma unroll
    for (int i = 0; i < 8; i++) {
        const int j2 = tid + i * 256;
        arow[j2] = __floats2half2_rn(v[2 * i] * inv, v[2 * i + 1] * inv);
    }
}

// ===========================================================================
extern "C" void kernel_launch(void* const* d_in, const int* in_sizes, int n_in,
                              void* d_out, int out_size)
{
    const float* feats = (const float*)d_in[0];
    float* out = (float*)d_out;

    __half *sims, *xh, *ah;
    cudaGetSymbolAddress((void**)&sims, g_sims);
    cudaGetSymbolAddress((void**)&xh, g_xh);
    cudaGetSymbolAddress((void**)&ah, g_ah);

    cudaFuncSetAttribute((void*)gemm_sym,
                         cudaFuncAttributeMaxDynamicSharedMemorySize, SMEM1);
    cudaFuncSetAttribute((void*)gemm_full,
                         cudaFuncAttributeMaxDynamicSharedMemorySize, SMEM2);

    // 1) feats -> fp16
    conv_f16<<<(NMAT * (size_t)NMAT / 4) / 256, 256>>>(feats, xh);

    // 2) sims = feats @ feats^T / 4096  (symmetric: upper tiles + mirror)
    gemm_sym<<<dim3(32, 32), 256, SMEM1>>>(xh, sims, 1.0f / 4096.0f);

    // 3) softmax rows (diag masked) -> fp16 attn
    softmax_rows<<<NMAT, 256>>>(sims, ah);

    // 4) out = attn @ feats^T / 64  (128x64 tiles, 3 CTAs/SM)
    gemm_full<<<dim3(64, 32), 128, SMEM2>>>(ah, xh, out, 1.0f / 64.0f);
}